// round 2
// baseline (speedup 1.0000x reference)
#include <cuda_runtime.h>
#include <cuda_bf16.h>

#define N_IN       1024
#define BATCH      1024
#define DEG        32
#define N_LAYERS   9
#define TOTAL_COLS 18432      // 1024 + 8*2048 + 1024
#define OUT_COL_BASE 17408
#define N_PHASES   11         // transpose-in, 9 layers, transpose-out

// Column-major value buffer: g_vals[col * BATCH + b]  (75.5 MB scratch)
__device__ float g_vals[TOTAL_COLS * BATCH];

// Persistent-kernel coordination state (reset each launch by init_kernel)
__device__ unsigned int g_work[N_PHASES];  // work-stealing counters, one per phase
__device__ unsigned int g_arrive;          // cumulative barrier arrivals
__device__ unsigned int g_release;         // highest released phase

__global__ void init_kernel() {
    int t = threadIdx.x;
    if (t < N_PHASES) g_work[t] = 0u;
    if (t == 0) { g_arrive = 0u; g_release = 0u; }
}

// Grid-wide barrier: phase p barrier releases once all nblocks arrived p times.
__device__ __forceinline__ void grid_barrier(unsigned phase, unsigned nblocks) {
    __syncthreads();
    if (threadIdx.x == 0) {
        __threadfence();  // release: make this block's g_vals writes visible
        unsigned arrived = atomicAdd(&g_arrive, 1u) + 1u;
        if (arrived == nblocks * phase) {
            atomicExch(&g_release, phase);
        } else {
            while (*(volatile unsigned*)&g_release < phase) { __nanosleep(64); }
        }
    }
    __syncthreads();  // all threads see barrier passed (acquire via control dep)
}

__global__ void __launch_bounds__(256) net_kernel(
    const float* __restrict__ X,
    const float* __restrict__ w_ptr,
    const int*   __restrict__ child_idx,
    float*       __restrict__ out,
    unsigned nblocks)
{
    const int t  = threadIdx.x;
    const int tx = t & 31, ty = t >> 5;   // 32x8 layout for transpose tiles

    __shared__ unsigned s_item;
    __shared__ int      sidx[DEG];
    __shared__ float    tile[32][33];

    const float w = *w_ptr;

    // ---------------- Phase 0: transpose X (row-major) -> g_vals (col-major)
    for (;;) {
        __syncthreads();                       // protect s_item / tile reuse
        if (t == 0) s_item = atomicAdd(&g_work[0], 1u);
        __syncthreads();
        unsigned item = s_item;
        if (item >= 32u * 32u) break;
        int bx = (int)(item & 31u) * 32;       // feature (column) tile base
        int by = (int)(item >> 5) * 32;        // batch tile base
        #pragma unroll
        for (int i = 0; i < 32; i += 8)
            tile[ty + i][tx] = X[(by + ty + i) * N_IN + (bx + tx)];
        __syncthreads();
        #pragma unroll
        for (int i = 0; i < 32; i += 8)
            g_vals[(bx + ty + i) * BATCH + (by + tx)] = tile[tx][ty + i];
    }

    // ---------------- Phases 1..9: layers
    const float4* vals4 = reinterpret_cast<const float4*>(g_vals);
    float4*       vals4w = reinterpret_cast<float4*>(g_vals);

    int idx_base = 0;
    int col_base = N_IN;
    for (int li = 0; li < N_LAYERS; li++) {
        const int sz = (li == N_LAYERS - 1) ? 1024 : 2048;
        const unsigned phase = 1u + (unsigned)li;

        grid_barrier(phase, nblocks);  // previous phase's writes complete

        for (;;) {
            __syncthreads();                   // protect s_item / sidx reuse
            if (t == 0) s_item = atomicAdd(&g_work[phase], 1u);
            __syncthreads();
            unsigned item = s_item;
            if (item >= (unsigned)sz) break;

            if (t < DEG) sidx[t] = child_idx[((size_t)idx_base + item) * DEG + t];
            __syncthreads();

            float4 a0 = make_float4(0.f, 0.f, 0.f, 0.f);
            float4 a1 = make_float4(0.f, 0.f, 0.f, 0.f);
            float4 a2 = make_float4(0.f, 0.f, 0.f, 0.f);
            float4 a3 = make_float4(0.f, 0.f, 0.f, 0.f);

            #pragma unroll
            for (int k = 0; k < DEG; k += 4) {
                float4 v0 = vals4[(size_t)sidx[k]     * (BATCH / 4) + t];
                float4 v1 = vals4[(size_t)sidx[k + 1] * (BATCH / 4) + t];
                float4 v2 = vals4[(size_t)sidx[k + 2] * (BATCH / 4) + t];
                float4 v3 = vals4[(size_t)sidx[k + 3] * (BATCH / 4) + t];
                a0.x += v0.x; a0.y += v0.y; a0.z += v0.z; a0.w += v0.w;
                a1.x += v1.x; a1.y += v1.y; a1.z += v1.z; a1.w += v1.w;
                a2.x += v2.x; a2.y += v2.y; a2.z += v2.z; a2.w += v2.w;
                a3.x += v3.x; a3.y += v3.y; a3.z += v3.z; a3.w += v3.w;
            }

            float4 o;
            o.x = tanhf(w * ((a0.x + a1.x) + (a2.x + a3.x)));
            o.y = tanhf(w * ((a0.y + a1.y) + (a2.y + a3.y)));
            o.z = tanhf(w * ((a0.z + a1.z) + (a2.z + a3.z)));
            o.w = tanhf(w * ((a0.w + a1.w) + (a2.w + a3.w)));

            vals4w[(size_t)(col_base + (int)item) * (BATCH / 4) + t] = o;
        }

        idx_base += sz;
        col_base += sz;
    }

    // ---------------- Phase 10: transpose last 1024 cols -> out (row-major)
    grid_barrier(10u, nblocks);
    for (;;) {
        __syncthreads();
        if (t == 0) s_item = atomicAdd(&g_work[10], 1u);
        __syncthreads();
        unsigned item = s_item;
        if (item >= 32u * 32u) break;
        int b0 = (int)(item & 31u) * 32;       // batch tile base
        int c0 = (int)(item >> 5) * 32;        // output-column tile base
        #pragma unroll
        for (int i = 0; i < 32; i += 8)
            tile[ty + i][tx] =
                g_vals[(size_t)(OUT_COL_BASE + c0 + ty + i) * BATCH + (b0 + tx)];
        __syncthreads();
        #pragma unroll
        for (int i = 0; i < 32; i += 8)
            out[(size_t)(b0 + ty + i) * 1024 + (c0 + tx)] = tile[tx][ty + i];
    }
}

// ---------------------------------------------------------------------------
extern "C" void kernel_launch(void* const* d_in, const int* in_sizes, int n_in,
                              void* d_out, int out_size) {
    const float* X         = (const float*)d_in[0];
    const float* w         = (const float*)d_in[1];
    const int*   child_idx = (const int*)d_in[2];
    float*       out       = (float*)d_out;
    (void)in_sizes; (void)n_in; (void)out_size;

    // Size grid to guaranteed co-residency (barrier safety).
    int dev = 0;
    cudaGetDevice(&dev);
    int sms = 0;
    cudaDeviceGetAttribute(&sms, cudaDevAttrMultiProcessorCount, dev);
    int per_sm = 0;
    cudaOccupancyMaxActiveBlocksPerMultiprocessor(&per_sm, net_kernel, 256, 0);
    if (per_sm < 1) per_sm = 1;
    unsigned grid = (unsigned)(sms * per_sm);
    if (grid > 2048u) grid = 2048u;

    init_kernel<<<1, 32>>>();
    net_kernel<<<grid, 256>>>(X, w, child_idx, out, grid);
}

// round 4
// speedup vs baseline: 1.1061x; 1.1061x over previous
#include <cuda_runtime.h>

#define N_IN       1024
#define BATCH      1024
#define DEG        32
#define N_LAYERS   9
#define TOTAL_COLS 18432
#define N_TANH     (TOTAL_COLS - N_IN)   // 17408 neuron-output columns
#define OUT_TCOL_BASE (N_TANH - 1024)    // 16384: tanh-col of first output col
#define QS   32767.0f
#define QINV (1.0f / 32767.0f)

// Column-major storage.
// Input region: fp32, 1024 cols x 1024 batch (4 MB).
__device__ float g_in[N_IN * BATCH];
// Neuron outputs: int16 Q15, 17408 cols x 1024 batch (34 MB).
__device__ short g_tanh[N_TANH * BATCH];
// Per-neuron reordered child indices (input-region first) + input count.
__device__ int g_reidx[N_TANH * DEG];
__device__ int g_ncnt[N_TANH];

// ---------------------------------------------------------------------------
// Partition each neuron's 32 child indices: input-region (idx<1024, kept as-is)
// first, then tanh-region (stored as idx-1024). Deterministic, graph-capturable.
// ---------------------------------------------------------------------------
__global__ void prep_kernel(const int* __restrict__ child_idx) {
    int n = blockIdx.x * 256 + threadIdx.x;
    if (n >= N_TANH) return;
    const int* src = child_idx + n * DEG;
    int buf_in[DEG], buf_t[DEG];
    int nin = 0, nt = 0;
    #pragma unroll
    for (int k = 0; k < DEG; k++) {
        int idx = src[k];
        if (idx < N_IN) buf_in[nin++] = idx;
        else            buf_t[nt++]   = idx - N_IN;
    }
    int* dst = g_reidx + n * DEG;
    for (int i = 0; i < nin; i++) dst[i]       = buf_in[i];
    for (int i = 0; i < nt;  i++) dst[nin + i] = buf_t[i];
    g_ncnt[n] = nin;
}

// ---------------------------------------------------------------------------
// Transpose X (BATCH x N_IN row-major fp32) -> g_in (col-major fp32).
// ---------------------------------------------------------------------------
__global__ void transpose_in_kernel(const float* __restrict__ X) {
    __shared__ float tile[32][33];
    int bx = blockIdx.x * 32;   // feature tile base
    int by = blockIdx.y * 32;   // batch tile base
    int tx = threadIdx.x, ty = threadIdx.y;
    #pragma unroll
    for (int i = 0; i < 32; i += 8)
        tile[ty + i][tx] = X[(by + ty + i) * N_IN + (bx + tx)];
    __syncthreads();
    #pragma unroll
    for (int i = 0; i < 32; i += 8)
        g_in[(bx + ty + i) * BATCH + (by + tx)] = tile[tx][ty + i];
}

// ---------------------------------------------------------------------------
// One layer: block computes neuron (neuron_base + blockIdx.x) for all 1024
// batch elements. Thread t owns batch elems 4t..4t+3.
// Gathers: fp32 float4 from input region, short4 from tanh region (exact
// integer accumulation), then pre = w*(fsum + isum/32767), out = tanh(pre),
// stored as int16 Q15.
// ---------------------------------------------------------------------------
__global__ void __launch_bounds__(256) layer_kernel(
    const float* __restrict__ w_ptr, int neuron_base)
{
    const int n = neuron_base + blockIdx.x;
    const int t = threadIdx.x;

    __shared__ int sidx[DEG];
    __shared__ int s_nin;
    if (t < DEG) sidx[t] = g_reidx[n * DEG + t];
    if (t == 0)  s_nin   = g_ncnt[n];
    __syncthreads();
    const int nin = s_nin;

    const float4* in4 = reinterpret_cast<const float4*>(g_in);
    const short4* th4 = reinterpret_cast<const short4*>(g_tanh);

    float fx = 0.f, fy = 0.f, fz = 0.f, fw = 0.f;
    #pragma unroll 4
    for (int k = 0; k < nin; k++) {
        float4 v = in4[sidx[k] * (BATCH / 4) + t];
        fx += v.x; fy += v.y; fz += v.z; fw += v.w;
    }

    int ix = 0, iy = 0, iz = 0, iw = 0;
    #pragma unroll 4
    for (int k = nin; k < DEG; k++) {
        short4 s = th4[sidx[k] * (BATCH / 4) + t];
        ix += s.x; iy += s.y; iz += s.z; iw += s.w;
    }

    const float w = __ldg(w_ptr);
    float ox = tanhf(w * fmaf((float)ix, QINV, fx));
    float oy = tanhf(w * fmaf((float)iy, QINV, fy));
    float oz = tanhf(w * fmaf((float)iz, QINV, fz));
    float ow = tanhf(w * fmaf((float)iw, QINV, fw));

    short4 o;
    o.x = (short)__float2int_rn(ox * QS);
    o.y = (short)__float2int_rn(oy * QS);
    o.z = (short)__float2int_rn(oz * QS);
    o.w = (short)__float2int_rn(ow * QS);
    reinterpret_cast<short4*>(g_tanh)[n * (BATCH / 4) + t] = o;
}

// ---------------------------------------------------------------------------
// Transpose last 1024 tanh cols (int16 col-major) -> out (BATCH x 1024 fp32).
// ---------------------------------------------------------------------------
__global__ void transpose_out_kernel(float* __restrict__ out) {
    __shared__ float tile[32][33];
    int b0 = blockIdx.x * 32;   // batch tile base
    int c0 = blockIdx.y * 32;   // output-column tile base
    int tx = threadIdx.x, ty = threadIdx.y;
    #pragma unroll
    for (int i = 0; i < 32; i += 8)
        tile[ty + i][tx] = (float)
            g_tanh[(size_t)(OUT_TCOL_BASE + c0 + ty + i) * BATCH + (b0 + tx)]
            * QINV;
    __syncthreads();
    #pragma unroll
    for (int i = 0; i < 32; i += 8)
        out[(size_t)(b0 + ty + i) * 1024 + (c0 + tx)] = tile[tx][ty + i];
}

// ---------------------------------------------------------------------------
extern "C" void kernel_launch(void* const* d_in, const int* in_sizes, int n_in,
                              void* d_out, int out_size) {
    const float* X         = (const float*)d_in[0];
    const float* w         = (const float*)d_in[1];
    const int*   child_idx = (const int*)d_in[2];
    float*       out       = (float*)d_out;
    (void)in_sizes; (void)n_in; (void)out_size;

    dim3 tgrid(32, 32), tblock(32, 8);

    prep_kernel<<<(N_TANH + 255) / 256, 256>>>(child_idx);
    transpose_in_kernel<<<tgrid, tblock>>>(X);

    static const int layer_sizes[N_LAYERS] =
        {2048, 2048, 2048, 2048, 2048, 2048, 2048, 2048, 1024};

    int neuron_base = 0;
    for (int li = 0; li < N_LAYERS; li++) {
        int sz = layer_sizes[li];
        layer_kernel<<<sz, 256>>>(w, neuron_base);
        neuron_base += sz;
    }

    transpose_out_kernel<<<tgrid, tblock>>>(out);
}

// round 5
// speedup vs baseline: 1.5771x; 1.4259x over previous
#include <cuda_runtime.h>

#define N_IN       1024
#define BATCH      1024
#define DEG        32
#define N_LAYERS   9
#define TOTAL_COLS 18432
#define OUT_COL_BASE 17408

// fp32 input, column-major (read only by layer 1) — 4 MB
__device__ float g_in[N_IN * BATCH];
// Unified int16 buffer, column-major: cols 0..1023 quantized input,
// cols 1024.. tanh outputs. Single scale g_s. 37.7 MB.
__device__ short g_q[(size_t)TOTAL_COLS * BATCH];
// Dynamic quantization scale state
__device__ unsigned g_maxbits;
__device__ float g_s, g_is;

__global__ void init_kernel() { g_maxbits = 0u; }

__global__ void maxabs_kernel(const float* __restrict__ X) {
    float m = 0.f;
    for (int i = blockIdx.x * 256 + threadIdx.x; i < N_IN * BATCH;
         i += gridDim.x * 256)
        m = fmaxf(m, fabsf(X[i]));
    #pragma unroll
    for (int o = 16; o; o >>= 1)
        m = fmaxf(m, __shfl_xor_sync(0xFFFFFFFFu, m, o));
    if ((threadIdx.x & 31) == 0)
        atomicMax(&g_maxbits, __float_as_uint(m));  // non-negative floats: bit order = value order
}

__global__ void scale_kernel() {
    float m = __uint_as_float(g_maxbits);
    if (m < 1.0f) m = 1.0f;          // tanh range must also fit
    float s = 32000.0f / m;
    g_s = s;
    g_is = 1.0f / s;
}

// ---------------------------------------------------------------------------
// Transpose X (row-major fp32) -> g_in (col-major fp32) + g_q (quantized int16)
// ---------------------------------------------------------------------------
__global__ void transpose_in_kernel(const float* __restrict__ X) {
    __shared__ float tile[32][33];
    int bx = blockIdx.x * 32, by = blockIdx.y * 32;
    int tx = threadIdx.x, ty = threadIdx.y;
    #pragma unroll
    for (int i = 0; i < 32; i += 8)
        tile[ty + i][tx] = X[(by + ty + i) * N_IN + (bx + tx)];
    __syncthreads();
    const float s = g_s;
    #pragma unroll
    for (int i = 0; i < 32; i += 8) {
        float v = tile[tx][ty + i];
        int col = bx + ty + i, b = by + tx;
        g_in[col * BATCH + b] = v;
        g_q[(size_t)col * BATCH + b] = (short)__float2int_rn(v * s);
    }
}

// ---------------------------------------------------------------------------
// Layer 1: all 32 children are input columns -> exact fp32 gathers (proven
// R1 structure, hits L2 cap). Output quantized to g_q col (1024 + j).
// ---------------------------------------------------------------------------
__global__ void __launch_bounds__(256) layer1_kernel(
    const int* __restrict__ child_idx, const float* __restrict__ w_ptr)
{
    const int j = blockIdx.x, t = threadIdx.x;
    __shared__ int sidx[DEG];
    if (t < DEG) sidx[t] = child_idx[j * DEG + t];
    __syncthreads();

    const float4* in4 = reinterpret_cast<const float4*>(g_in);
    float4 a0 = make_float4(0.f,0.f,0.f,0.f), a1 = make_float4(0.f,0.f,0.f,0.f);
    #pragma unroll
    for (int k = 0; k < DEG; k += 2) {
        float4 v0 = in4[sidx[k]     * (BATCH / 4) + t];
        float4 v1 = in4[sidx[k + 1] * (BATCH / 4) + t];
        a0.x += v0.x; a0.y += v0.y; a0.z += v0.z; a0.w += v0.w;
        a1.x += v1.x; a1.y += v1.y; a1.z += v1.z; a1.w += v1.w;
    }

    const float w = __ldg(w_ptr), s = g_s;
    short4 o;
    o.x = (short)__float2int_rn(tanhf(w * (a0.x + a1.x)) * s);
    o.y = (short)__float2int_rn(tanhf(w * (a0.y + a1.y)) * s);
    o.z = (short)__float2int_rn(tanhf(w * (a0.z + a1.z)) * s);
    o.w = (short)__float2int_rn(tanhf(w * (a0.w + a1.w)) * s);
    reinterpret_cast<short4*>(g_q)[(size_t)(N_IN + j) * (BATCH / 4) + t] = o;
}

// ---------------------------------------------------------------------------
// Layers 2..9: uniform int16 gathers from g_q using RAW child indices.
// 128 threads, each owns 8 batch elems (one uint4 = 8 int16). Exact integer
// accumulation via DP2A (1 instr per element). Static full unroll.
// ---------------------------------------------------------------------------
__global__ void __launch_bounds__(128) layerN_kernel(
    const int* __restrict__ child_idx, const float* __restrict__ w_ptr,
    int col_base)
{
    const int j = blockIdx.x, t = threadIdx.x;  // t: 0..127, 8 elems each
    __shared__ int sidx[DEG];
    if (t < DEG) sidx[t] = child_idx[j * DEG + t];
    __syncthreads();

    const uint4* q4 = reinterpret_cast<const uint4*>(g_q);  // col = 128 uint4

    int a0=0,a1=0,a2=0,a3=0,a4=0,a5=0,a6=0,a7=0;
    #pragma unroll
    for (int k = 0; k < DEG; k++) {
        uint4 v = q4[(size_t)sidx[k] * (BATCH / 8) + t];
        a0 = __dp2a_lo((int)v.x, 0x0001, a0);  // low  int16 of v.x
        a1 = __dp2a_lo((int)v.x, 0x0100, a1);  // high int16 of v.x
        a2 = __dp2a_lo((int)v.y, 0x0001, a2);
        a3 = __dp2a_lo((int)v.y, 0x0100, a3);
        a4 = __dp2a_lo((int)v.z, 0x0001, a4);
        a5 = __dp2a_lo((int)v.z, 0x0100, a5);
        a6 = __dp2a_lo((int)v.w, 0x0001, a6);
        a7 = __dp2a_lo((int)v.w, 0x0100, a7);
    }

    const float w = __ldg(w_ptr), is = g_is, s = g_s;
    const float ws = w * is;

    int q0 = __float2int_rn(tanhf(ws * (float)a0) * s);
    int q1 = __float2int_rn(tanhf(ws * (float)a1) * s);
    int q2 = __float2int_rn(tanhf(ws * (float)a2) * s);
    int q3 = __float2int_rn(tanhf(ws * (float)a3) * s);
    int q4_ = __float2int_rn(tanhf(ws * (float)a4) * s);
    int q5 = __float2int_rn(tanhf(ws * (float)a5) * s);
    int q6 = __float2int_rn(tanhf(ws * (float)a6) * s);
    int q7 = __float2int_rn(tanhf(ws * (float)a7) * s);

    uint4 o;
    o.x = (q0 & 0xFFFF) | (q1 << 16);
    o.y = (q2 & 0xFFFF) | (q3 << 16);
    o.z = (q4_ & 0xFFFF) | (q5 << 16);
    o.w = (q6 & 0xFFFF) | (q7 << 16);
    reinterpret_cast<uint4*>(g_q)[(size_t)(col_base + j) * (BATCH / 8) + t] = o;
}

// ---------------------------------------------------------------------------
// Transpose last 1024 cols of g_q -> out (BATCH x 1024 fp32), dequantized.
// ---------------------------------------------------------------------------
__global__ void transpose_out_kernel(float* __restrict__ out) {
    __shared__ float tile[32][33];
    int b0 = blockIdx.x * 32, c0 = blockIdx.y * 32;
    int tx = threadIdx.x, ty = threadIdx.y;
    const float is = g_is;
    #pragma unroll
    for (int i = 0; i < 32; i += 8)
        tile[ty + i][tx] = (float)
            g_q[(size_t)(OUT_COL_BASE + c0 + ty + i) * BATCH + (b0 + tx)] * is;
    __syncthreads();
    #pragma unroll
    for (int i = 0; i < 32; i += 8)
        out[(size_t)(b0 + ty + i) * 1024 + (c0 + tx)] = tile[tx][ty + i];
}

// ---------------------------------------------------------------------------
extern "C" void kernel_launch(void* const* d_in, const int* in_sizes, int n_in,
                              void* d_out, int out_size) {
    const float* X         = (const float*)d_in[0];
    const float* w         = (const float*)d_in[1];
    const int*   child_idx = (const int*)d_in[2];
    float*       out       = (float*)d_out;
    (void)in_sizes; (void)n_in; (void)out_size;

    dim3 tgrid(32, 32), tblock(32, 8);

    init_kernel<<<1, 1>>>();
    maxabs_kernel<<<64, 256>>>(X);
    scale_kernel<<<1, 1>>>();
    transpose_in_kernel<<<tgrid, tblock>>>(X);

    static const int layer_sizes[N_LAYERS] =
        {2048, 2048, 2048, 2048, 2048, 2048, 2048, 2048, 1024};

    layer1_kernel<<<2048, 256>>>(child_idx, w);

    int idx_base = 2048;
    int col_base = N_IN + 2048;
    for (int li = 1; li < N_LAYERS; li++) {
        int sz = layer_sizes[li];
        layerN_kernel<<<sz, 128>>>(child_idx + (size_t)idx_base * DEG, w, col_base);
        idx_base += sz;
        col_base += sz;
    }

    transpose_out_kernel<<<tgrid, tblock>>>(out);
}

// round 6
// speedup vs baseline: 1.8510x; 1.1737x over previous
#include <cuda_runtime.h>

#define N_IN       1024
#define BATCH      1024
#define DEG        32
#define N_LAYERS   9
#define TOTAL_COLS 18432
#define OUT_COL_BASE 17408

// Unified int16 Q buffer, column-major: cols 0..1023 quantized input,
// cols 1024..18431 tanh outputs. Single dynamic scale g_s. 37.7 MB.
__device__ short g_q[(size_t)TOTAL_COLS * BATCH];
// Dynamic quantization scale state
__device__ unsigned g_maxbits;
__device__ float g_s, g_is;

__global__ void init_kernel() { g_maxbits = 0u; }

__global__ void maxabs_kernel(const float* __restrict__ X) {
    const float4* X4 = reinterpret_cast<const float4*>(X);
    float m = 0.f;
    for (int i = blockIdx.x * 256 + threadIdx.x; i < (N_IN * BATCH) / 4;
         i += gridDim.x * 256) {
        float4 v = X4[i];
        m = fmaxf(m, fmaxf(fmaxf(fabsf(v.x), fabsf(v.y)),
                           fmaxf(fabsf(v.z), fabsf(v.w))));
    }
    #pragma unroll
    for (int o = 16; o; o >>= 1)
        m = fmaxf(m, __shfl_xor_sync(0xFFFFFFFFu, m, o));
    if ((threadIdx.x & 31) == 0)
        atomicMax(&g_maxbits, __float_as_uint(m));  // non-neg floats: bit order = value order
}

__global__ void scale_kernel() {
    float m = __uint_as_float(g_maxbits);
    if (m < 1.0f) m = 1.0f;          // tanh outputs (|v|<1) must also fit
    float s = 32000.0f / m;
    g_s = s;
    g_is = 1.0f / s;
}

// ---------------------------------------------------------------------------
// Transpose X (BATCH x N_IN row-major fp32) -> g_q cols 0..1023 (int16).
// ---------------------------------------------------------------------------
__global__ void transpose_in_kernel(const float* __restrict__ X) {
    __shared__ float tile[32][33];
    int bx = blockIdx.x * 32, by = blockIdx.y * 32;
    int tx = threadIdx.x, ty = threadIdx.y;
    #pragma unroll
    for (int i = 0; i < 32; i += 8)
        tile[ty + i][tx] = X[(by + ty + i) * N_IN + (bx + tx)];
    __syncthreads();
    const float s = g_s;
    #pragma unroll
    for (int i = 0; i < 32; i += 8)
        g_q[(size_t)(bx + ty + i) * BATCH + (by + tx)] =
            (short)__float2int_rn(tile[tx][ty + i] * s);
}

// ---------------------------------------------------------------------------
// One layer: block j computes neuron (col_base + j) for all 1024 batch elems.
// 128 threads, each owns 8 batch elems (one uint4 = 8 int16). Exact integer
// accumulation via DP2A (1 instr/element). Raw child indices hit the unified
// buffer directly (input cols and tanh cols share one scale).
// ---------------------------------------------------------------------------
__global__ void __launch_bounds__(128) layer_kernel(
    const int* __restrict__ child_idx, const float* __restrict__ w_ptr,
    int col_base)
{
    const int j = blockIdx.x, t = threadIdx.x;  // t: 0..127
    __shared__ int sidx[DEG];
    if (t < DEG) sidx[t] = child_idx[j * DEG + t];
    __syncthreads();

    const uint4* q4 = reinterpret_cast<const uint4*>(g_q);  // col = 128 uint4

    int a0=0,a1=0,a2=0,a3=0,a4=0,a5=0,a6=0,a7=0;
    #pragma unroll
    for (int k = 0; k < DEG; k++) {
        uint4 v = q4[(size_t)sidx[k] * (BATCH / 8) + t];
        a0 = __dp2a_lo((int)v.x, 0x0001, a0);  // low  int16
        a1 = __dp2a_lo((int)v.x, 0x0100, a1);  // high int16
        a2 = __dp2a_lo((int)v.y, 0x0001, a2);
        a3 = __dp2a_lo((int)v.y, 0x0100, a3);
        a4 = __dp2a_lo((int)v.z, 0x0001, a4);
        a5 = __dp2a_lo((int)v.z, 0x0100, a5);
        a6 = __dp2a_lo((int)v.w, 0x0001, a6);
        a7 = __dp2a_lo((int)v.w, 0x0100, a7);
    }

    const float w = __ldg(w_ptr), is = g_is, s = g_s;
    const float ws = w * is;

    int q0 = __float2int_rn(tanhf(ws * (float)a0) * s);
    int q1 = __float2int_rn(tanhf(ws * (float)a1) * s);
    int q2 = __float2int_rn(tanhf(ws * (float)a2) * s);
    int q3 = __float2int_rn(tanhf(ws * (float)a3) * s);
    int q4_ = __float2int_rn(tanhf(ws * (float)a4) * s);
    int q5 = __float2int_rn(tanhf(ws * (float)a5) * s);
    int q6 = __float2int_rn(tanhf(ws * (float)a6) * s);
    int q7 = __float2int_rn(tanhf(ws * (float)a7) * s);

    uint4 o;
    o.x = (q0 & 0xFFFF) | (q1 << 16);
    o.y = (q2 & 0xFFFF) | (q3 << 16);
    o.z = (q4_ & 0xFFFF) | (q5 << 16);
    o.w = (q6 & 0xFFFF) | (q7 << 16);
    reinterpret_cast<uint4*>(g_q)[(size_t)(col_base + j) * (BATCH / 8) + t] = o;
}

// ---------------------------------------------------------------------------
// Transpose last 1024 cols of g_q -> out (BATCH x 1024 fp32), dequantized.
// ---------------------------------------------------------------------------
__global__ void transpose_out_kernel(float* __restrict__ out) {
    __shared__ float tile[32][33];
    int b0 = blockIdx.x * 32, c0 = blockIdx.y * 32;
    int tx = threadIdx.x, ty = threadIdx.y;
    const float is = g_is;
    #pragma unroll
    for (int i = 0; i < 32; i += 8)
        tile[ty + i][tx] = (float)
            g_q[(size_t)(OUT_COL_BASE + c0 + ty + i) * BATCH + (b0 + tx)] * is;
    __syncthreads();
    #pragma unroll
    for (int i = 0; i < 32; i += 8)
        out[(size_t)(b0 + ty + i) * 1024 + (c0 + tx)] = tile[tx][ty + i];
}

// ---------------------------------------------------------------------------
extern "C" void kernel_launch(void* const* d_in, const int* in_sizes, int n_in,
                              void* d_out, int out_size) {
    const float* X         = (const float*)d_in[0];
    const float* w         = (const float*)d_in[1];
    const int*   child_idx = (const int*)d_in[2];
    float*       out       = (float*)d_out;
    (void)in_sizes; (void)n_in; (void)out_size;

    dim3 tgrid(32, 32), tblock(32, 8);

    init_kernel<<<1, 1>>>();
    maxabs_kernel<<<64, 256>>>(X);
    scale_kernel<<<1, 1>>>();
    transpose_in_kernel<<<tgrid, tblock>>>(X);

    static const int layer_sizes[N_LAYERS] =
        {2048, 2048, 2048, 2048, 2048, 2048, 2048, 2048, 1024};

    int idx_base = 0;
    int col_base = N_IN;
    for (int li = 0; li < N_LAYERS; li++) {
        int sz = layer_sizes[li];
        layer_kernel<<<sz, 128>>>(child_idx + (size_t)idx_base * DEG, w, col_base);
        idx_base += sz;
        col_base += sz;
    }

    transpose_out_kernel<<<tgrid, tblock>>>(out);
}